// round 2
// baseline (speedup 1.0000x reference)
#include <cuda_runtime.h>
#include <cuda_bf16.h>

// ---------------------------------------------------------------------------
// RQ-spline coupling flow log-prob, fused.
// F=16, H1=H2=64, K=8, L=8, NBP=25. B = in_sizes[0]/16.
//
// Algebraic reductions vs reference:
//  * mz has only 8 nonzero features  -> W0 stage is 8x16
//  * no activation between W2 and Wout -> precompute Wf = W2@Wout (64 x 200
//    used columns only: the 8 transformed features per layer), bf = b2@Wout+bout
//  * per-layer sum(log|scale|) precomputed
// ---------------------------------------------------------------------------

#define BLK 128

// padded layout: 8 features * 28 params (25 used, 3 pad) = 224 cols
__device__ __align__(16) float g_Wf[8 * 64 * 224];
__device__ __align__(16) float g_bf[8 * 224];
__device__ float g_lc[8];

__global__ void precompute_kernel(const float* __restrict__ W2,
                                  const float* __restrict__ b2,
                                  const float* __restrict__ Wout,
                                  const float* __restrict__ bout,
                                  const float* __restrict__ scale) {
    const int NWF = 8 * 64 * 224;
    const int NBF = 8 * 224;
    int idx = blockIdx.x * blockDim.x + threadIdx.x;
    if (idx < NWF) {
        int l = idx / (64 * 224);
        int r = idx % (64 * 224);
        int k = r / 224;
        int c = r % 224;
        int t = c / 28, p = c % 28;
        float v = 0.0f;
        if (p < 25) {
            int col = (2 * t + (l & 1)) * 25 + p;       // transformed feature 2t+(l&1)
            const float* w2row = W2 + l * 4096 + k * 64;
            const float* wo = Wout + l * 25600 + col;
            #pragma unroll 8
            for (int j = 0; j < 64; j++) v += w2row[j] * wo[j * 400];
        }
        g_Wf[idx] = v;
    } else if (idx < NWF + NBF) {
        int e = idx - NWF;
        int l = e / 224;
        int c = e % 224;
        int t = c / 28, p = c % 28;
        float v = 0.0f;
        if (p < 25) {
            int col = (2 * t + (l & 1)) * 25 + p;
            const float* b2r = b2 + l * 64;
            const float* wo = Wout + l * 25600 + col;
            #pragma unroll 8
            for (int j = 0; j < 64; j++) v += b2r[j] * wo[j * 400];
            v += bout[l * 400 + col];
        }
        g_bf[e] = v;
    } else if (idx < NWF + NBF + 8) {
        int l = idx - NWF - NBF;
        float v = 0.0f;
        for (int f = 0; f < 16; f++) v += logf(fabsf(scale[l * 16 + f]));
        g_lc[l] = v;
    }
}

__device__ __forceinline__ float fast_tanh(float x) {
    float cx = fminf(fmaxf(x, -15.0f), 15.0f);
    float e = __expf(2.0f * cx);
    return __fdividef(e - 1.0f, e + 1.0f);
}

__device__ __forceinline__ float softplus_f(float t) {
    float r = __logf(1.0f + __expf(t));
    return (t > 20.0f) ? t : r;
}

__global__ __launch_bounds__(BLK)
void flow_kernel(const float* __restrict__ x,
                 const float* __restrict__ W0g, const float* __restrict__ b0g,
                 const float* __restrict__ W1g, const float* __restrict__ b1g,
                 const float* __restrict__ scaleg, const float* __restrict__ shiftg,
                 float* __restrict__ out, int B) {
    extern __shared__ float sm[];
    float* sW0 = sm;            // 256
    float* sb0 = sm + 256;      // 16
    float* sW1 = sm + 272;      // 1024
    float* sb1 = sm + 1296;     // 64
    float* ssc = sm + 1360;     // 16
    float* ssh = sm + 1376;     // 16
    float* sbf = sm + 1392;     // 224
    float* sWf = sm + 1616;     // 64*224 = 14336 (16B aligned: 1616*4 % 16 == 0)
    float* sh1 = sm + 15952;    // 64*BLK

    const int tid = threadIdx.x;
    const int row = blockIdx.x * BLK + tid;
    const bool valid = row < B;

    // z split by feature parity: za[t] = feature 2t, zb[t] = feature 2t+1
    float za[8], zb[8];
    if (valid) {
        const float4* xr = (const float4*)(x + (size_t)row * 16);
        #pragma unroll
        for (int q = 0; q < 4; q++) {
            float4 v = xr[q];
            za[2 * q + 0] = v.x; zb[2 * q + 0] = v.y;
            za[2 * q + 1] = v.z; zb[2 * q + 1] = v.w;
        }
    } else {
        #pragma unroll
        for (int t = 0; t < 8; t++) { za[t] = 0.0f; zb[t] = 0.0f; }
    }

    float logdet = 0.0f;

    #pragma unroll 1
    for (int l = 7; l >= 0; --l) {
        __syncthreads();
        // -------- stage weights into smem --------
        for (int i = tid; i < 256; i += BLK)  sW0[i] = W0g[l * 256 + i];
        for (int i = tid; i < 1024; i += BLK) sW1[i] = W1g[l * 1024 + i];
        if (tid < 64) sb1[tid] = b1g[l * 64 + tid];
        if (tid < 16) {
            sb0[tid] = b0g[l * 16 + tid];
            ssc[tid] = scaleg[l * 16 + tid];
            ssh[tid] = shiftg[l * 16 + tid];
        }
        for (int i = tid; i < 224; i += BLK) sbf[i] = g_bf[l * 224 + i];
        {
            const float4* src = (const float4*)(g_Wf + l * 14336);
            float4* dst = (float4*)sWf;
            for (int i = tid; i < 3584; i += BLK) dst[i] = src[i];
        }
        __syncthreads();

        const int par = l & 1;  // transformed features have parity == par

        // -------- stage 0: h0 = tanh(mz @ W0 + b0), mz = kept (parity 1-par) --------
        float h0[16];
        #pragma unroll
        for (int j = 0; j < 16; ++j) {
            float a = sb0[j];
            #pragma unroll
            for (int t = 0; t < 8; ++t) {
                float zk = par ? za[t] : zb[t];       // kept parity = 1-par
                int fk = 2 * t + 1 - par;
                a += zk * sW0[fk * 16 + j];
            }
            h0[j] = fast_tanh(a);
        }

        // -------- stage 1: h1 = tanh(h0 @ W1 + b1) --------
        float h1[64];
        #pragma unroll
        for (int j = 0; j < 64; ++j) h1[j] = sb1[j];
        #pragma unroll
        for (int k = 0; k < 16; ++k) {
            float hk = h0[k];
            const float4* wr = (const float4*)(sW1 + k * 64);
            #pragma unroll
            for (int j4 = 0; j4 < 16; ++j4) {
                float4 w = wr[j4];
                h1[4 * j4 + 0] += hk * w.x;
                h1[4 * j4 + 1] += hk * w.y;
                h1[4 * j4 + 2] += hk * w.z;
                h1[4 * j4 + 3] += hk * w.w;
            }
        }
        #pragma unroll
        for (int j = 0; j < 64; ++j) sh1[j * BLK + tid] = fast_tanh(h1[j]);

        // -------- stage 2 + spline, per transformed feature --------
        #pragma unroll
        for (int t = 0; t < 8; ++t) {
            float acc[25];
            #pragma unroll
            for (int p = 0; p < 25; ++p) acc[p] = sbf[t * 28 + p];

            #pragma unroll 4
            for (int k = 0; k < 64; ++k) {
                float hk = sh1[k * BLK + tid];
                const float4* w4 = (const float4*)(sWf + k * 224 + t * 28);
                #pragma unroll
                for (int q = 0; q < 6; ++q) {
                    float4 w = w4[q];
                    acc[4 * q + 0] += hk * w.x;
                    acc[4 * q + 1] += hk * w.y;
                    acc[4 * q + 2] += hk * w.z;
                    acc[4 * q + 3] += hk * w.w;
                }
                acc[24] += hk * sWf[k * 224 + t * 28 + 24];
            }

            // ---- RQ spline forward + log-det ----
            float xv = par ? zb[t] : za[t];

            float mw = acc[0];
            #pragma unroll
            for (int k = 1; k < 8; ++k) mw = fmaxf(mw, acc[k]);
            float ew[8]; float swsum = 0.0f;
            #pragma unroll
            for (int k = 0; k < 8; ++k) { ew[k] = __expf(acc[k] - mw); swsum += ew[k]; }
            float cw = __fdividef(19.9992f, swsum);   // widths = ew*cw + 1e-4

            float mh = acc[8];
            #pragma unroll
            for (int k = 1; k < 8; ++k) mh = fmaxf(mh, acc[8 + k]);
            float eh[8]; float shsum = 0.0f;
            #pragma unroll
            for (int k = 0; k < 8; ++k) { eh[k] = __expf(acc[8 + k] - mh); shsum += eh[k]; }
            float chh = __fdividef(19.9992f, shsum);

            // bin search over cumulative widths
            float cum = -10.0f;
            float xk = -10.0f;
            int idx = 0;
            #pragma unroll
            for (int k = 0; k < 7; ++k) {
                cum += ew[k] * cw + 1e-4f;
                if (xv >= cum) { xk = cum; idx = k + 1; }
            }

            // select bin quantities (predicated — no dynamic reg indexing)
            float yk = -10.0f, bh = 0.0f, bw = 1.0f, udk = 0.0f, udk1 = 0.0f;
            #pragma unroll
            for (int k = 0; k < 8; ++k) {
                float hh = eh[k] * chh + 1e-4f;
                if (k < idx) yk += hh;
                if (k == idx) {
                    bh = hh;
                    bw = ew[k] * cw + 1e-4f;
                    udk = acc[16 + k];
                    udk1 = acc[17 + k];
                }
            }

            float dk  = softplus_f(udk  + 0.54116665f) + 1e-4f;
            float dk1 = softplus_f(udk1 + 0.54116665f) + 1e-4f;
            float s   = __fdividef(bh, bw);
            float zt  = __saturatef(__fdividef(xv - xk, bw));
            float z1  = 1.0f - zt;
            float zz  = zt * zt;
            float zz1 = zt * z1;
            float den = s + (dk1 + dk - 2.0f * s) * zz1;
            float y   = yk + bh * __fdividef(s * zz + dk * zz1, den);
            float numld = dk1 * zz + 2.0f * s * zz1 + dk * z1 * z1;
            float ld = 2.0f * __logf(s) + __logf(numld) - 2.0f * __logf(den);

            bool outside = (xv <= -10.0f) || (xv >= 10.0f);
            if (outside) { y = xv; ld = 0.0f; }

            if (par) zb[t] = y; else za[t] = y;
            logdet += ld;
        }

        // -------- affine: z = z*scale + shift (all features) --------
        #pragma unroll
        for (int t = 0; t < 8; ++t) {
            za[t] = za[t] * ssc[2 * t]     + ssh[2 * t];
            zb[t] = zb[t] * ssc[2 * t + 1] + ssh[2 * t + 1];
        }
        logdet += g_lc[l];
    }

    float ss = 0.0f;
    #pragma unroll
    for (int t = 0; t < 8; ++t) ss += za[t] * za[t] + zb[t] * zb[t];

    if (valid) out[row] = -0.5f * ss - 14.703170f + logdet;  // 8*log(2*pi)=14.70317...
}

extern "C" void kernel_launch(void* const* d_in, const int* in_sizes, int n_in,
                              void* d_out, int out_size) {
    const float* x     = (const float*)d_in[0];
    const float* W0    = (const float*)d_in[1];
    const float* b0    = (const float*)d_in[2];
    const float* W1    = (const float*)d_in[3];
    const float* b1    = (const float*)d_in[4];
    const float* W2    = (const float*)d_in[5];
    const float* b2    = (const float*)d_in[6];
    const float* Wout  = (const float*)d_in[7];
    const float* bout  = (const float*)d_in[8];
    const float* scale = (const float*)d_in[9];
    const float* shift = (const float*)d_in[10];

    int B = in_sizes[0] / 16;

    const int NP = 8 * 64 * 224 + 8 * 224 + 8;
    precompute_kernel<<<(NP + 255) / 256, 256>>>(W2, b2, Wout, bout, scale);

    size_t smem = (size_t)(15952 + 64 * BLK) * sizeof(float);  // 96576 B
    cudaFuncSetAttribute(flow_kernel, cudaFuncAttributeMaxDynamicSharedMemorySize,
                         (int)smem);
    flow_kernel<<<(B + BLK - 1) / BLK, BLK, smem>>>(
        x, W0, b0, W1, b1, scale, shift, (float*)d_out, B);
}

// round 6
// speedup vs baseline: 1.7226x; 1.7226x over previous
#include <cuda_runtime.h>
#include <cuda_bf16.h>
#include <cstdint>

// ---------------------------------------------------------------------------
// RQ-spline coupling flow log-prob, fused. Stage-2 GEMM on tensor cores via
// warp-level mma.sync (m16n8k16 bf16, 3xBF16 split precision ~ fp32 accuracy).
// F=16, H1=H2=64, K=8, L=8, NBP=25.
//
//  * mz has only 8 nonzero features          -> W0 stage is 8x16 (scalar)
//  * no activation between W2 and Wout       -> Wf = W2@Wout precomputed;
//    only the 8 transformed features' 25 params kept, padded to 8x32 = 256 cols
//  * stage-2 [BLK x 64] @ [64 x 256] per CTA/layer on mma.sync bf16, D=f32,
//    3 passes: AhBh + AhBm + AmBh  (error ~2^-17)
// ---------------------------------------------------------------------------

#define BLK 256          // threads per CTA = rows per CTA (8 warps, 32 rows/warp)

// B operand Wf^T, [l][n=256][k=64] bf16, hi & mid split parts
__device__ __align__(16) unsigned short g_Bhi[8 * 256 * 64];
__device__ __align__(16) unsigned short g_Bmid[8 * 256 * 64];
__device__ __align__(16) float g_bf[8 * 256];    // bias, padded t*32+p layout
__device__ float g_lc[8];

// ---------------- precompute: Wf = W2@Wout, transposed, bf16 hi/mid --------
__global__ void precompute_kernel(const float* __restrict__ W2,
                                  const float* __restrict__ b2,
                                  const float* __restrict__ Wout,
                                  const float* __restrict__ bout,
                                  const float* __restrict__ scale) {
    const int NWF = 8 * 256 * 64;
    const int NBF = 8 * 256;
    int idx = blockIdx.x * blockDim.x + threadIdx.x;
    if (idx < NWF) {
        int l = idx / 16384;
        int r = idx % 16384;
        int n = r / 64;             // padded output col: t*32 + p
        int k = r % 64;             // h1 index
        int t = n >> 5, p = n & 31;
        float v = 0.0f;
        if (p < 25) {
            int col = (2 * t + (l & 1)) * 25 + p;   // transformed feature 2t+(l&1)
            const float* w2row = W2 + l * 4096 + k * 64;
            const float* wo = Wout + l * 25600 + col;
            #pragma unroll 8
            for (int j = 0; j < 64; j++) v += w2row[j] * wo[j * 400];
        }
        __nv_bfloat16 h = __float2bfloat16_rn(v);
        float rm = v - __bfloat162float(h);
        __nv_bfloat16 m = __float2bfloat16_rn(rm);
        g_Bhi[idx]  = __bfloat16_as_ushort(h);
        g_Bmid[idx] = __bfloat16_as_ushort(m);
    } else if (idx < NWF + NBF) {
        int e = idx - NWF;
        int l = e / 256;
        int n = e % 256;
        int t = n >> 5, p = n & 31;
        float v = 0.0f;
        if (p < 25) {
            int col = (2 * t + (l & 1)) * 25 + p;
            const float* b2r = b2 + l * 64;
            const float* wo = Wout + l * 25600 + col;
            #pragma unroll 8
            for (int j = 0; j < 64; j++) v += b2r[j] * wo[j * 400];
            v += bout[l * 400 + col];
        }
        g_bf[e] = v;
    } else if (idx < NWF + NBF + 8) {
        int l = idx - NWF - NBF;
        float v = 0.0f;
        for (int f = 0; f < 16; f++) v += logf(fabsf(scale[l * 16 + f]));
        g_lc[l] = v;
    }
}

__device__ __forceinline__ float fast_tanh(float x) {
    float cx = fminf(fmaxf(x, -15.0f), 15.0f);
    float e = __expf(2.0f * cx);
    return __fdividef(e - 1.0f, e + 1.0f);
}
__device__ __forceinline__ float softplus_f(float t) {
    float r = __logf(1.0f + __expf(t));
    return (t > 20.0f) ? t : r;
}

__device__ __forceinline__ void mma_bf16(float& d0, float& d1, float& d2, float& d3,
                                         uint32_t a0, uint32_t a1, uint32_t a2, uint32_t a3,
                                         uint32_t b0, uint32_t b1) {
    asm volatile(
        "mma.sync.aligned.m16n8k16.row.col.f32.bf16.bf16.f32 "
        "{%0,%1,%2,%3}, {%4,%5,%6,%7}, {%8,%9}, {%0,%1,%2,%3};"
        : "+f"(d0), "+f"(d1), "+f"(d2), "+f"(d3)
        : "r"(a0), "r"(a1), "r"(a2), "r"(a3), "r"(b0), "r"(b1));
}

// ---------------- smem layout (bytes) ----------------
// small weights: 1648 floats -> 6592 B, round to 6656
static constexpr int SM_W    = 0;
static constexpr int SM_AHI  = 6656;                    // BLK x 64 bf16, row stride 144B
static constexpr int SM_AMID = SM_AHI  + BLK * 144;     // 36864 each (BLK=256)
static constexpr int SM_BHI  = SM_AMID + BLK * 144;     // 256 n x 64 k bf16, stride 144B
static constexpr int SM_BMID = SM_BHI  + 256 * 144;
static constexpr int SM_PAR  = SM_BMID + 256 * 144;     // 8 warps x 32 rows x 33 cols f32
static constexpr int SM_TOTAL = SM_PAR + 8 * 32 * 33 * 4;   // = 187904 B

__global__ __launch_bounds__(BLK, 1)
void flow_kernel(const float* __restrict__ x,
                 const float* __restrict__ W0g, const float* __restrict__ b0g,
                 const float* __restrict__ W1g, const float* __restrict__ b1g,
                 const float* __restrict__ scaleg, const float* __restrict__ shiftg,
                 float* __restrict__ out, int B) {
    extern __shared__ __align__(16) char smem[];

    float* sW0 = (float*)(smem + SM_W);   // 256
    float* sb0 = sW0 + 256;               // 16
    float* sW1 = sb0 + 16;                // 1024
    float* sb1 = sW1 + 1024;              // 64
    float* ssc = sb1 + 64;                // 16
    float* ssh = ssc + 16;                // 16
    float* sbf = ssh + 16;                // 256

    const int tid  = threadIdx.x;
    const int w    = tid >> 5;            // warp id (0..7)
    const int lane = tid & 31;
    const int g    = lane >> 2;           // mma fragment group row
    const int q    = lane & 3;            // mma fragment quad col
    const int row  = blockIdx.x * BLK + tid;
    const bool valid = row < B;

    // z split by feature parity: za[t]=feat 2t, zb[t]=feat 2t+1
    float za[8], zb[8];
    if (valid) {
        const float4* xr = (const float4*)(x + (size_t)row * 16);
        #pragma unroll
        for (int qq = 0; qq < 4; qq++) {
            float4 v = xr[qq];
            za[2 * qq] = v.x;     zb[2 * qq] = v.y;
            za[2 * qq + 1] = v.z; zb[2 * qq + 1] = v.w;
        }
    } else {
        #pragma unroll
        for (int t = 0; t < 8; t++) { za[t] = 0.0f; zb[t] = 0.0f; }
    }

    float logdet = 0.0f;

    #pragma unroll 1
    for (int l = 7; l >= 0; --l) {
        __syncthreads();   // protect smem reuse from previous layer

        // -------- stage small weights + B tiles into smem --------
        sW0[tid] = W0g[l * 256 + tid];                        // 256 == BLK
        for (int i = tid; i < 1024; i += BLK) sW1[i] = W1g[l * 1024 + i];
        if (tid < 64) sb1[tid] = b1g[l * 64 + tid];
        if (tid < 16) {
            sb0[tid] = b0g[l * 16 + tid];
            ssc[tid] = scaleg[l * 16 + tid];
            ssh[tid] = shiftg[l * 16 + tid];
        }
        sbf[tid] = g_bf[l * 256 + tid];
        {
            // thread tid copies B row tid (64 bf16 = 8 uint4) for both parts
            const uint4* srcH = (const uint4*)(g_Bhi  + l * 16384) + tid * 8;
            const uint4* srcM = (const uint4*)(g_Bmid + l * 16384) + tid * 8;
            uint4* dstH = (uint4*)(smem + SM_BHI  + tid * 144);
            uint4* dstM = (uint4*)(smem + SM_BMID + tid * 144);
            #pragma unroll
            for (int i = 0; i < 8; i++) { dstH[i] = srcH[i]; dstM[i] = srcM[i]; }
        }
        __syncthreads();

        const int par = l & 1;

        // -------- stage 0: h0 = tanh(mz @ W0 + b0) --------
        float h0[16];
        #pragma unroll
        for (int j = 0; j < 16; ++j) {
            float a = sb0[j];
            #pragma unroll
            for (int t = 0; t < 8; ++t) {
                float zk = par ? za[t] : zb[t];     // kept parity = 1-par
                int fk = 2 * t + 1 - par;
                a += zk * sW0[fk * 16 + j];
            }
            h0[j] = fast_tanh(a);
        }

        // -------- stage 1: h1 = tanh(h0 @ W1 + b1) --------
        float h1[64];
        #pragma unroll
        for (int j = 0; j < 64; ++j) h1[j] = sb1[j];
        #pragma unroll
        for (int k = 0; k < 16; ++k) {
            float hk = h0[k];
            const float4* wr = (const float4*)(sW1 + k * 64);
            #pragma unroll
            for (int j4 = 0; j4 < 16; ++j4) {
                float4 wv = wr[j4];
                h1[4 * j4 + 0] += hk * wv.x;
                h1[4 * j4 + 1] += hk * wv.y;
                h1[4 * j4 + 2] += hk * wv.z;
                h1[4 * j4 + 3] += hk * wv.w;
            }
        }

        // -------- split h1 into bf16 hi/mid, store A rows to smem --------
        {
            uint32_t packH[32], packM[32];
            #pragma unroll
            for (int i = 0; i < 32; ++i) {
                float v0 = fast_tanh(h1[2 * i]);
                float v1 = fast_tanh(h1[2 * i + 1]);
                __nv_bfloat16 h0b = __float2bfloat16_rn(v0);
                __nv_bfloat16 h1b = __float2bfloat16_rn(v1);
                float r0 = v0 - __bfloat162float(h0b);
                float r1 = v1 - __bfloat162float(h1b);
                __nv_bfloat16 m0b = __float2bfloat16_rn(r0);
                __nv_bfloat16 m1b = __float2bfloat16_rn(r1);
                packH[i] = (uint32_t)__bfloat16_as_ushort(h0b) |
                           ((uint32_t)__bfloat16_as_ushort(h1b) << 16);
                packM[i] = (uint32_t)__bfloat16_as_ushort(m0b) |
                           ((uint32_t)__bfloat16_as_ushort(m1b) << 16);
            }
            uint4* dh = (uint4*)(smem + SM_AHI  + tid * 144);
            uint4* dm = (uint4*)(smem + SM_AMID + tid * 144);
            #pragma unroll
            for (int i = 0; i < 8; i++) {
                dh[i] = make_uint4(packH[4*i], packH[4*i+1], packH[4*i+2], packH[4*i+3]);
                dm[i] = make_uint4(packM[4*i], packM[4*i+1], packM[4*i+2], packM[4*i+3]);
            }
        }
        __syncthreads();

        // -------- hoist A fragments (warp's 32 rows, all 4 k-steps, hi+mid) --------
        // A[r][k] b32 at byte r*144 + k*2;  frag: r = 32w+16m+g (+8), k = 2q+16ks (+8)
        uint32_t Ah[2][4][4], Am[2][4][4];
        #pragma unroll
        for (int m = 0; m < 2; ++m) {
            const char* baseH = smem + SM_AHI  + (32 * w + 16 * m + g) * 144 + q * 4;
            const char* baseM = smem + SM_AMID + (32 * w + 16 * m + g) * 144 + q * 4;
            #pragma unroll
            for (int ks = 0; ks < 4; ++ks) {
                int o = ks * 32;
                Ah[m][ks][0] = *(const uint32_t*)(baseH + o);
                Ah[m][ks][1] = *(const uint32_t*)(baseH + o + 8 * 144);
                Ah[m][ks][2] = *(const uint32_t*)(baseH + o + 16);
                Ah[m][ks][3] = *(const uint32_t*)(baseH + o + 8 * 144 + 16);
                Am[m][ks][0] = *(const uint32_t*)(baseM + o);
                Am[m][ks][1] = *(const uint32_t*)(baseM + o + 8 * 144);
                Am[m][ks][2] = *(const uint32_t*)(baseM + o + 16);
                Am[m][ks][3] = *(const uint32_t*)(baseM + o + 8 * 144 + 16);
            }
        }

        float* pwarp = (float*)(smem + SM_PAR + w * 4224);   // [32][33]

        // -------- per transformed feature: mma + spline --------
        #pragma unroll 1
        for (int t = 0; t < 8; ++t) {
            #pragma unroll
            for (int j = 0; j < 4; ++j) {
                // B fragments for this n-tile: col n = t*32 + 8j + g, k = 2q+16ks (+8)
                uint32_t Bh[4][2], Bm[4][2];
                const char* bbH = smem + SM_BHI  + (t * 32 + 8 * j + g) * 144 + q * 4;
                const char* bbM = smem + SM_BMID + (t * 32 + 8 * j + g) * 144 + q * 4;
                #pragma unroll
                for (int ks = 0; ks < 4; ++ks) {
                    int o = ks * 32;
                    Bh[ks][0] = *(const uint32_t*)(bbH + o);
                    Bh[ks][1] = *(const uint32_t*)(bbH + o + 16);
                    Bm[ks][0] = *(const uint32_t*)(bbM + o);
                    Bm[ks][1] = *(const uint32_t*)(bbM + o + 16);
                }
                #pragma unroll
                for (int m = 0; m < 2; ++m) {
                    float d0 = 0.0f, d1 = 0.0f, d2 = 0.0f, d3 = 0.0f;
                    #pragma unroll
                    for (int ks = 0; ks < 4; ++ks) {
                        mma_bf16(d0, d1, d2, d3,
                                 Ah[m][ks][0], Ah[m][ks][1], Ah[m][ks][2], Ah[m][ks][3],
                                 Bh[ks][0], Bh[ks][1]);
                        mma_bf16(d0, d1, d2, d3,
                                 Ah[m][ks][0], Ah[m][ks][1], Ah[m][ks][2], Ah[m][ks][3],
                                 Bm[ks][0], Bm[ks][1]);
                        mma_bf16(d0, d1, d2, d3,
                                 Am[m][ks][0], Am[m][ks][1], Am[m][ks][2], Am[m][ks][3],
                                 Bh[ks][0], Bh[ks][1]);
                    }
                    // scatter D to padded params buffer
                    int r0 = 16 * m + g;
                    int c0 = 8 * j + 2 * q;
                    pwarp[r0 * 33 + c0]           = d0;
                    pwarp[r0 * 33 + c0 + 1]       = d1;
                    pwarp[(r0 + 8) * 33 + c0]     = d2;
                    pwarp[(r0 + 8) * 33 + c0 + 1] = d3;
                }
            }
            __syncwarp();

            // gather this thread's row params + bias
            float acc[25];
            {
                const float* pr = pwarp + lane * 33;
                #pragma unroll
                for (int p = 0; p < 25; ++p) acc[p] = pr[p] + sbf[t * 32 + p];
            }
            __syncwarp();   // params buffer free for next feature

            // ---- RQ spline forward + log-det ----
            float xv = par ? zb[t] : za[t];

            float mw = acc[0];
            #pragma unroll
            for (int k = 1; k < 8; ++k) mw = fmaxf(mw, acc[k]);
            float ew[8]; float swsum = 0.0f;
            #pragma unroll
            for (int k = 0; k < 8; ++k) { ew[k] = __expf(acc[k] - mw); swsum += ew[k]; }
            float cw = __fdividef(19.9992f, swsum);

            float mh = acc[8];
            #pragma unroll
            for (int k = 1; k < 8; ++k) mh = fmaxf(mh, acc[8 + k]);
            float eh[8]; float shsum = 0.0f;
            #pragma unroll
            for (int k = 0; k < 8; ++k) { eh[k] = __expf(acc[8 + k] - mh); shsum += eh[k]; }
            float chh = __fdividef(19.9992f, shsum);

            float cum = -10.0f, xk = -10.0f;
            int idx = 0;
            #pragma unroll
            for (int k = 0; k < 7; ++k) {
                cum += ew[k] * cw + 1e-4f;
                if (xv >= cum) { xk = cum; idx = k + 1; }
            }

            float yk = -10.0f, bh = 0.0f, bw = 1.0f, udk = 0.0f, udk1 = 0.0f;
            #pragma unroll
            for (int k = 0; k < 8; ++k) {
                float hh = eh[k] * chh + 1e-4f;
                if (k < idx) yk += hh;
                if (k == idx) {
                    bh = hh;
                    bw = ew[k] * cw + 1e-4f;
                    udk = acc[16 + k];
                    udk1 = acc[17 + k];
                }
            }

            float dk  = softplus_f(udk  + 0.54116665f) + 1e-4f;
            float dk1 = softplus_f(udk1 + 0.54116665f) + 1e-4f;
            float s   = __fdividef(bh, bw);
            float zt  = __saturatef(__fdividef(xv - xk, bw));
            float z1  = 1.0f - zt;
            float zz  = zt * zt;
            float zz1 = zt * z1;
            float den = s + (dk1 + dk - 2.0f * s) * zz1;
            float y   = yk + bh * __fdividef(s * zz + dk * zz1, den);
            float numld = dk1 * zz + 2.0f * s * zz1 + dk * z1 * z1;
            float ld = 2.0f * __logf(s) + __logf(numld) - 2.0f * __logf(den);

            bool outside = (xv <= -10.0f) || (xv >= 10.0f);
            if (outside) { y = xv; ld = 0.0f; }

            if (par) zb[t] = y; else za[t] = y;
            logdet += ld;
        }

        // -------- affine: z = z*scale + shift --------
        #pragma unroll
        for (int t = 0; t < 8; ++t) {
            za[t] = za[t] * ssc[2 * t]     + ssh[2 * t];
            zb[t] = zb[t] * ssc[2 * t + 1] + ssh[2 * t + 1];
        }
        logdet += g_lc[l];
    }

    float ss = 0.0f;
    #pragma unroll
    for (int t = 0; t < 8; ++t) ss += za[t] * za[t] + zb[t] * zb[t];

    if (valid) out[row] = -0.5f * ss - 14.703170f + logdet;   // 8*log(2*pi)
}

extern "C" void kernel_launch(void* const* d_in, const int* in_sizes, int n_in,
                              void* d_out, int out_size) {
    const float* x     = (const float*)d_in[0];
    const float* W0    = (const float*)d_in[1];
    const float* b0    = (const float*)d_in[2];
    const float* W1    = (const float*)d_in[3];
    const float* b1    = (const float*)d_in[4];
    const float* W2    = (const float*)d_in[5];
    const float* b2    = (const float*)d_in[6];
    const float* Wout  = (const float*)d_in[7];
    const float* bout  = (const float*)d_in[8];
    const float* scale = (const float*)d_in[9];
    const float* shift = (const float*)d_in[10];

    int B = in_sizes[0] / 16;

    const int NP = 8 * 256 * 64 + 8 * 256 + 8;
    precompute_kernel<<<(NP + 255) / 256, 256>>>(W2, b2, Wout, bout, scale);

    cudaFuncSetAttribute(flow_kernel, cudaFuncAttributeMaxDynamicSharedMemorySize, SM_TOTAL);
    flow_kernel<<<(B + BLK - 1) / BLK, BLK, SM_TOTAL>>>(
        x, W0, b0, W1, b1, scale, shift, (float*)d_out, B);
}

// round 7
// speedup vs baseline: 1.7619x; 1.0228x over previous
#include <cuda_runtime.h>
#include <cuda_bf16.h>
#include <cstdint>

// ---------------------------------------------------------------------------
// RQ-spline coupling flow log-prob, fused. Stage-2 GEMM on tensor cores via
// warp-level mma.sync (m16n8k16 bf16, 3xBF16 split precision ~ fp32 accuracy).
// F=16, H1=H2=64, K=8, L=8, NBP=25.
//
// R6 -> R7: BLK 256->384 (12 warps/SM, latency hiding), PAR buffer aliased
// onto dead A-hi smem region (keeps smem at 191KB), extra sync after A-frag
// hoist to make the aliasing race-free.
// ---------------------------------------------------------------------------

#define BLK 384          // threads per CTA = rows per CTA (12 warps)

// B operand Wf^T, [l][n=256][k=64] bf16, hi & mid split parts
__device__ __align__(16) unsigned short g_Bhi[8 * 256 * 64];
__device__ __align__(16) unsigned short g_Bmid[8 * 256 * 64];
__device__ __align__(16) float g_bf[8 * 256];    // bias, padded t*32+p layout
__device__ float g_lc[8];

// ---------------- precompute: Wf = W2@Wout, transposed, bf16 hi/mid --------
__global__ void precompute_kernel(const float* __restrict__ W2,
                                  const float* __restrict__ b2,
                                  const float* __restrict__ Wout,
                                  const float* __restrict__ bout,
                                  const float* __restrict__ scale) {
    const int NWF = 8 * 256 * 64;
    const int NBF = 8 * 256;
    int idx = blockIdx.x * blockDim.x + threadIdx.x;
    if (idx < NWF) {
        int l = idx / 16384;
        int r = idx % 16384;
        int n = r / 64;             // padded output col: t*32 + p
        int k = r % 64;             // h1 index
        int t = n >> 5, p = n & 31;
        float v = 0.0f;
        if (p < 25) {
            int col = (2 * t + (l & 1)) * 25 + p;   // transformed feature 2t+(l&1)
            const float* w2row = W2 + l * 4096 + k * 64;
            const float* wo = Wout + l * 25600 + col;
            #pragma unroll 8
            for (int j = 0; j < 64; j++) v += w2row[j] * wo[j * 400];
        }
        __nv_bfloat16 h = __float2bfloat16_rn(v);
        float rm = v - __bfloat162float(h);
        __nv_bfloat16 m = __float2bfloat16_rn(rm);
        g_Bhi[idx]  = __bfloat16_as_ushort(h);
        g_Bmid[idx] = __bfloat16_as_ushort(m);
    } else if (idx < NWF + NBF) {
        int e = idx - NWF;
        int l = e / 256;
        int n = e % 256;
        int t = n >> 5, p = n & 31;
        float v = 0.0f;
        if (p < 25) {
            int col = (2 * t + (l & 1)) * 25 + p;
            const float* b2r = b2 + l * 64;
            const float* wo = Wout + l * 25600 + col;
            #pragma unroll 8
            for (int j = 0; j < 64; j++) v += b2r[j] * wo[j * 400];
            v += bout[l * 400 + col];
        }
        g_bf[e] = v;
    } else if (idx < NWF + NBF + 8) {
        int l = idx - NWF - NBF;
        float v = 0.0f;
        for (int f = 0; f < 16; f++) v += logf(fabsf(scale[l * 16 + f]));
        g_lc[l] = v;
    }
}

__device__ __forceinline__ float fast_tanh(float x) {
    float cx = fminf(fmaxf(x, -15.0f), 15.0f);
    float e = __expf(2.0f * cx);
    return __fdividef(e - 1.0f, e + 1.0f);
}
__device__ __forceinline__ float softplus_f(float t) {
    float r = __logf(1.0f + __expf(t));
    return (t > 20.0f) ? t : r;
}

__device__ __forceinline__ void mma_bf16(float& d0, float& d1, float& d2, float& d3,
                                         uint32_t a0, uint32_t a1, uint32_t a2, uint32_t a3,
                                         uint32_t b0, uint32_t b1) {
    asm volatile(
        "mma.sync.aligned.m16n8k16.row.col.f32.bf16.bf16.f32 "
        "{%0,%1,%2,%3}, {%4,%5,%6,%7}, {%8,%9}, {%0,%1,%2,%3};"
        : "+f"(d0), "+f"(d1), "+f"(d2), "+f"(d3)
        : "r"(a0), "r"(a1), "r"(a2), "r"(a3), "r"(b0), "r"(b1));
}

// ---------------- smem layout (bytes) ----------------
// small weights: 1648 floats -> 6592 B, round to 6656
static constexpr int SM_W    = 0;
static constexpr int SM_AHI  = 6656;                    // BLK x 64 bf16, row stride 144B
static constexpr int SM_AMID = SM_AHI  + BLK * 144;     // 55296 each (BLK=384)
static constexpr int SM_BHI  = SM_AMID + BLK * 144;     // 256 n x 64 k bf16, stride 144B
static constexpr int SM_BMID = SM_BHI  + 256 * 144;
static constexpr int SM_TOTAL = SM_BMID + 256 * 144;    // = 190976 B
// PAR (D bounce, 12 warps x 32 rows x 33 f32 = 50688 B) aliases SM_AHI:
// A-hi region (55296 B) is dead after the A-fragment hoist; a __syncthreads()
// between hoist and first PAR write makes the aliasing race-free.
static constexpr int SM_PAR  = SM_AHI;

__global__ __launch_bounds__(BLK, 1)
void flow_kernel(const float* __restrict__ x,
                 const float* __restrict__ W0g, const float* __restrict__ b0g,
                 const float* __restrict__ W1g, const float* __restrict__ b1g,
                 const float* __restrict__ scaleg, const float* __restrict__ shiftg,
                 float* __restrict__ out, int B) {
    extern __shared__ __align__(16) char smem[];

    float* sW0 = (float*)(smem + SM_W);   // 256
    float* sb0 = sW0 + 256;               // 16
    float* sW1 = sb0 + 16;                // 1024
    float* sb1 = sW1 + 1024;              // 64
    float* ssc = sb1 + 64;                // 16
    float* ssh = ssc + 16;                // 16
    float* sbf = ssh + 16;                // 256

    const int tid  = threadIdx.x;
    const int w    = tid >> 5;            // warp id (0..11)
    const int lane = tid & 31;
    const int g    = lane >> 2;           // mma fragment group row
    const int q    = lane & 3;            // mma fragment quad col
    const int row  = blockIdx.x * BLK + tid;
    const bool valid = row < B;

    // z split by feature parity: za[t]=feat 2t, zb[t]=feat 2t+1
    float za[8], zb[8];
    if (valid) {
        const float4* xr = (const float4*)(x + (size_t)row * 16);
        #pragma unroll
        for (int qq = 0; qq < 4; qq++) {
            float4 v = xr[qq];
            za[2 * qq] = v.x;     zb[2 * qq] = v.y;
            za[2 * qq + 1] = v.z; zb[2 * qq + 1] = v.w;
        }
    } else {
        #pragma unroll
        for (int t = 0; t < 8; t++) { za[t] = 0.0f; zb[t] = 0.0f; }
    }

    float logdet = 0.0f;

    #pragma unroll 1
    for (int l = 7; l >= 0; --l) {
        __syncthreads();   // protect smem (incl. aliased PAR/A) from previous layer

        // -------- stage small weights + B tiles into smem --------
        if (tid < 256) sW0[tid] = W0g[l * 256 + tid];
        for (int i = tid; i < 1024; i += BLK) sW1[i] = W1g[l * 1024 + i];
        if (tid < 64) sb1[tid] = b1g[l * 64 + tid];
        if (tid < 16) {
            sb0[tid] = b0g[l * 16 + tid];
            ssc[tid] = scaleg[l * 16 + tid];
            ssh[tid] = shiftg[l * 16 + tid];
        }
        if (tid < 256) sbf[tid] = g_bf[l * 256 + tid];
        if (tid < 256) {
            // thread tid copies B row tid (64 bf16 = 8 uint4) for both parts
            const uint4* srcH = (const uint4*)(g_Bhi  + l * 16384) + tid * 8;
            const uint4* srcM = (const uint4*)(g_Bmid + l * 16384) + tid * 8;
            uint4* dstH = (uint4*)(smem + SM_BHI  + tid * 144);
            uint4* dstM = (uint4*)(smem + SM_BMID + tid * 144);
            #pragma unroll
            for (int i = 0; i < 8; i++) { dstH[i] = srcH[i]; dstM[i] = srcM[i]; }
        }
        __syncthreads();

        const int par = l & 1;

        // -------- stage 0: h0 = tanh(mz @ W0 + b0) --------
        float h0[16];
        #pragma unroll
        for (int j = 0; j < 16; ++j) {
            float a = sb0[j];
            #pragma unroll
            for (int t = 0; t < 8; ++t) {
                float zk = par ? za[t] : zb[t];     // kept parity = 1-par
                int fk = 2 * t + 1 - par;
                a += zk * sW0[fk * 16 + j];
            }
            h0[j] = fast_tanh(a);
        }

        // -------- stage 1: h1 = tanh(h0 @ W1 + b1) --------
        float h1[64];
        #pragma unroll
        for (int j = 0; j < 64; ++j) h1[j] = sb1[j];
        #pragma unroll
        for (int k = 0; k < 16; ++k) {
            float hk = h0[k];
            const float4* wr = (const float4*)(sW1 + k * 64);
            #pragma unroll
            for (int j4 = 0; j4 < 16; ++j4) {
                float4 wv = wr[j4];
                h1[4 * j4 + 0] += hk * wv.x;
                h1[4 * j4 + 1] += hk * wv.y;
                h1[4 * j4 + 2] += hk * wv.z;
                h1[4 * j4 + 3] += hk * wv.w;
            }
        }

        // -------- split h1 into bf16 hi/mid, store A rows to smem --------
        {
            uint32_t packH[32], packM[32];
            #pragma unroll
            for (int i = 0; i < 32; ++i) {
                float v0 = fast_tanh(h1[2 * i]);
                float v1 = fast_tanh(h1[2 * i + 1]);
                __nv_bfloat16 h0b = __float2bfloat16_rn(v0);
                __nv_bfloat16 h1b = __float2bfloat16_rn(v1);
                float r0 = v0 - __bfloat162float(h0b);
                float r1 = v1 - __bfloat162float(h1b);
                __nv_bfloat16 m0b = __float2bfloat16_rn(r0);
                __nv_bfloat16 m1b = __float2bfloat16_rn(r1);
                packH[i] = (uint32_t)__bfloat16_as_ushort(h0b) |
                           ((uint32_t)__bfloat16_as_ushort(h1b) << 16);
                packM[i] = (uint32_t)__bfloat16_as_ushort(m0b) |
                           ((uint32_t)__bfloat16_as_ushort(m1b) << 16);
            }
            uint4* dh = (uint4*)(smem + SM_AHI  + tid * 144);
            uint4* dm = (uint4*)(smem + SM_AMID + tid * 144);
            #pragma unroll
            for (int i = 0; i < 8; i++) {
                dh[i] = make_uint4(packH[4*i], packH[4*i+1], packH[4*i+2], packH[4*i+3]);
                dm[i] = make_uint4(packM[4*i], packM[4*i+1], packM[4*i+2], packM[4*i+3]);
            }
        }
        __syncthreads();

        // -------- hoist A fragments (warp's 32 rows, all 4 k-steps, hi+mid) --------
        // A[r][k] b32 at byte r*144 + k*2;  frag: r = 32w+16m+g (+8), k = 2q+16ks (+8)
        uint32_t Ah[2][4][4], Am[2][4][4];
        #pragma unroll
        for (int m = 0; m < 2; ++m) {
            const char* baseH = smem + SM_AHI  + (32 * w + 16 * m + g) * 144 + q * 4;
            const char* baseM = smem + SM_AMID + (32 * w + 16 * m + g) * 144 + q * 4;
            #pragma unroll
            for (int ks = 0; ks < 4; ++ks) {
                int o = ks * 32;
                Ah[m][ks][0] = *(const uint32_t*)(baseH + o);
                Ah[m][ks][1] = *(const uint32_t*)(baseH + o + 8 * 144);
                Ah[m][ks][2] = *(const uint32_t*)(baseH + o + 16);
                Ah[m][ks][3] = *(const uint32_t*)(baseH + o + 8 * 144 + 16);
                Am[m][ks][0] = *(const uint32_t*)(baseM + o);
                Am[m][ks][1] = *(const uint32_t*)(baseM + o + 8 * 144);
                Am[m][ks][2] = *(const uint32_t*)(baseM + o + 16);
                Am[m][ks][3] = *(const uint32_t*)(baseM + o + 8 * 144 + 16);
            }
        }
        __syncthreads();   // all warps done reading A-hi -> PAR aliasing now safe

        float* pwarp = (float*)(smem + SM_PAR + w * 4224);   // [32][33]

        // -------- per transformed feature: mma + spline --------
        #pragma unroll 1
        for (int t = 0; t < 8; ++t) {
            #pragma unroll
            for (int j = 0; j < 4; ++j) {
                // B fragments for this n-tile: col n = t*32 + 8j + g, k = 2q+16ks (+8)
                uint32_t Bh[4][2], Bm[4][2];
                const char* bbH = smem + SM_BHI  + (t * 32 + 8 * j + g) * 144 + q * 4;
                const char* bbM = smem + SM_BMID + (t * 32 + 8 * j + g) * 144 + q * 4;
                #pragma unroll
                for (int ks = 0; ks < 4; ++ks) {
                    int o = ks * 32;
                    Bh[ks][0] = *(const uint32_t*)(bbH + o);
                    Bh[ks][1] = *(const uint32_t*)(bbH + o + 16);
                    Bm[ks][0] = *(const uint32_t*)(bbM + o);
                    Bm[ks][1] = *(const uint32_t*)(bbM + o + 16);
                }
                #pragma unroll
                for (int m = 0; m < 2; ++m) {
                    float d0 = 0.0f, d1 = 0.0f, d2 = 0.0f, d3 = 0.0f;
                    #pragma unroll
                    for (int ks = 0; ks < 4; ++ks) {
                        mma_bf16(d0, d1, d2, d3,
                                 Ah[m][ks][0], Ah[m][ks][1], Ah[m][ks][2], Ah[m][ks][3],
                                 Bh[ks][0], Bh[ks][1]);
                        mma_bf16(d0, d1, d2, d3,
                                 Ah[m][ks][0], Ah[m][ks][1], Ah[m][ks][2], Ah[m][ks][3],
                                 Bm[ks][0], Bm[ks][1]);
                        mma_bf16(d0, d1, d2, d3,
                                 Am[m][ks][0], Am[m][ks][1], Am[m][ks][2], Am[m][ks][3],
                                 Bh[ks][0], Bh[ks][1]);
                    }
                    // scatter D to padded params buffer
                    int r0 = 16 * m + g;
                    int c0 = 8 * j + 2 * q;
                    pwarp[r0 * 33 + c0]           = d0;
                    pwarp[r0 * 33 + c0 + 1]       = d1;
                    pwarp[(r0 + 8) * 33 + c0]     = d2;
                    pwarp[(r0 + 8) * 33 + c0 + 1] = d3;
                }
            }
            __syncwarp();

            // gather this thread's row params + bias
            float acc[25];
            {
                const float* pr = pwarp + lane * 33;
                #pragma unroll
                for (int p = 0; p < 25; ++p) acc[p] = pr[p] + sbf[t * 32 + p];
            }
            __syncwarp();   // params buffer free for next feature

            // ---- RQ spline forward + log-det ----
            float xv = par ? zb[t] : za[t];

            float mw = acc[0];
            #pragma unroll
            for (int k = 1; k < 8; ++k) mw = fmaxf(mw, acc[k]);
            float ew[8]; float swsum = 0.0f;
            #pragma unroll
            for (int k = 0; k < 8; ++k) { ew[k] = __expf(acc[k] - mw); swsum += ew[k]; }
            float cw = __fdividef(19.9992f, swsum);

            float mh = acc[8];
            #pragma unroll
            for (int k = 1; k < 8; ++k) mh = fmaxf(mh, acc[8 + k]);
            float eh[8]; float shsum = 0.0f;
            #pragma unroll
            for (int k = 0; k < 8; ++k) { eh[k] = __expf(acc[8 + k] - mh); shsum += eh[k]; }
            float chh = __fdividef(19.9992f, shsum);

            float cum = -10.0f, xk = -10.0f;
            int idx = 0;
            #pragma unroll
            for (int k = 0; k < 7; ++k) {
                cum += ew[k] * cw + 1e-4f;
                if (xv >= cum) { xk = cum; idx = k + 1; }
            }

            float yk = -10.0f, bh = 0.0f, bw = 1.0f, udk = 0.0f, udk1 = 0.0f;
            #pragma unroll
            for (int k = 0; k < 8; ++k) {
                float hh = eh[k] * chh + 1e-4f;
                if (k < idx) yk += hh;
                if (k == idx) {
                    bh = hh;
                    bw = ew[k] * cw + 1e-4f;
                    udk = acc[16 + k];
                    udk1 = acc[17 + k];
                }
            }

            float dk  = softplus_f(udk  + 0.54116665f) + 1e-4f;
            float dk1 = softplus_f(udk1 + 0.54116665f) + 1e-4f;
            float s   = __fdividef(bh, bw);
            float zt  = __saturatef(__fdividef(xv - xk, bw));
            float z1  = 1.0f - zt;
            float zz  = zt * zt;
            float zz1 = zt * z1;
            float den = s + (dk1 + dk - 2.0f * s) * zz1;
            float y   = yk + bh * __fdividef(s * zz + dk * zz1, den);
            float numld = dk1 * zz + 2.0f * s * zz1 + dk * z1 * z1;
            float ld = 2.0f * __logf(s) + __logf(numld) - 2.0f * __logf(den);

            bool outside = (xv <= -10.0f) || (xv >= 10.0f);
            if (outside) { y = xv; ld = 0.0f; }

            if (par) zb[t] = y; else za[t] = y;
            logdet += ld;
        }

        // -------- affine: z = z*scale + shift --------
        #pragma unroll
        for (int t = 0; t < 8; ++t) {
            za[t] = za[t] * ssc[2 * t]     + ssh[2 * t];
            zb[t] = zb[t] * ssc[2 * t + 1] + ssh[2 * t + 1];
        }
        logdet += g_lc[l];
    }

    float ss = 0.0f;
    #pragma unroll
    for (int t = 0; t < 8; ++t) ss += za[t] * za[t] + zb[t] * zb[t];

    if (valid) out[row] = -0.5f * ss - 14.703170f + logdet;   // 8*log(2*pi)
}

extern "C" void kernel_launch(void* const* d_in, const int* in_sizes, int n_in,
                              void* d_out, int out_size) {
    const float* x     = (const float*)d_in[0];
    const float* W0    = (const float*)d_in[1];
    const float* b0    = (const float*)d_in[2];
    const float* W1    = (const float*)d_in[3];
    const float* b1    = (const float*)d_in[4];
    const float* W2    = (const float*)d_in[5];
    const float* b2    = (const float*)d_in[6];
    const float* Wout  = (const float*)d_in[7];
    const float* bout  = (const float*)d_in[8];
    const float* scale = (const float*)d_in[9];
    const float* shift = (const float*)d_in[10];

    int B = in_sizes[0] / 16;

    const int NP = 8 * 256 * 64 + 8 * 256 + 8;
    precompute_kernel<<<(NP + 255) / 256, 256>>>(W2, b2, Wout, bout, scale);

    cudaFuncSetAttribute(flow_kernel, cudaFuncAttributeMaxDynamicSharedMemorySize, SM_TOTAL);
    flow_kernel<<<(B + BLK - 1) / BLK, BLK, SM_TOTAL>>>(
        x, W0, b0, W1, b1, scale, shift, (float*)d_out, B);
}

// round 10
// speedup vs baseline: 1.7946x; 1.0186x over previous
#include <cuda_runtime.h>
#include <cuda_bf16.h>
#include <cstdint>

// ---------------------------------------------------------------------------
// RQ-spline coupling flow log-prob, fused. Stage-2 GEMM on tensor cores via
// warp-level mma.sync (m16n8k16 bf16, 3xBF16 split precision ~ fp32 accuracy).
// F=16, H1=H2=64, K=8, L=8, NBP=25.
//
// R7 -> R8: ldmatrix.x4 for A/B fragment loads (4x fewer LSU instrs on the
// hottest path), D-bounce buffer stride 33->34 with float2 scatter/gather.
// ---------------------------------------------------------------------------

#define BLK 384          // threads per CTA = rows per CTA (12 warps)

// B operand Wf^T, [l][n=256][k=64] bf16, hi & mid split parts
__device__ __align__(16) unsigned short g_Bhi[8 * 256 * 64];
__device__ __align__(16) unsigned short g_Bmid[8 * 256 * 64];
__device__ __align__(16) float g_bf[8 * 256];    // bias, padded t*32+p layout
__device__ float g_lc[8];

// ---------------- precompute: Wf = W2@Wout, transposed, bf16 hi/mid --------
__global__ void precompute_kernel(const float* __restrict__ W2,
                                  const float* __restrict__ b2,
                                  const float* __restrict__ Wout,
                                  const float* __restrict__ bout,
                                  const float* __restrict__ scale) {
    const int NWF = 8 * 256 * 64;
    const int NBF = 8 * 256;
    int idx = blockIdx.x * blockDim.x + threadIdx.x;
    if (idx < NWF) {
        int l = idx / 16384;
        int r = idx % 16384;
        int n = r / 64;             // padded output col: t*32 + p
        int k = r % 64;             // h1 index
        int t = n >> 5, p = n & 31;
        float v = 0.0f;
        if (p < 25) {
            int col = (2 * t + (l & 1)) * 25 + p;   // transformed feature 2t+(l&1)
            const float* w2row = W2 + l * 4096 + k * 64;
            const float* wo = Wout + l * 25600 + col;
            #pragma unroll 8
            for (int j = 0; j < 64; j++) v += w2row[j] * wo[j * 400];
        }
        __nv_bfloat16 h = __float2bfloat16_rn(v);
        float rm = v - __bfloat162float(h);
        __nv_bfloat16 m = __float2bfloat16_rn(rm);
        g_Bhi[idx]  = __bfloat16_as_ushort(h);
        g_Bmid[idx] = __bfloat16_as_ushort(m);
    } else if (idx < NWF + NBF) {
        int e = idx - NWF;
        int l = e / 256;
        int n = e % 256;
        int t = n >> 5, p = n & 31;
        float v = 0.0f;
        if (p < 25) {
            int col = (2 * t + (l & 1)) * 25 + p;
            const float* b2r = b2 + l * 64;
            const float* wo = Wout + l * 25600 + col;
            #pragma unroll 8
            for (int j = 0; j < 64; j++) v += b2r[j] * wo[j * 400];
            v += bout[l * 400 + col];
        }
        g_bf[e] = v;
    } else if (idx < NWF + NBF + 8) {
        int l = idx - NWF - NBF;
        float v = 0.0f;
        for (int f = 0; f < 16; f++) v += logf(fabsf(scale[l * 16 + f]));
        g_lc[l] = v;
    }
}

__device__ __forceinline__ float fast_tanh(float x) {
    float cx = fminf(fmaxf(x, -15.0f), 15.0f);
    float e = __expf(2.0f * cx);
    return __fdividef(e - 1.0f, e + 1.0f);
}
__device__ __forceinline__ float softplus_f(float t) {
    float r = __logf(1.0f + __expf(t));
    return (t > 20.0f) ? t : r;
}

__device__ __forceinline__ void mma_bf16(float& d0, float& d1, float& d2, float& d3,
                                         uint32_t a0, uint32_t a1, uint32_t a2, uint32_t a3,
                                         uint32_t b0, uint32_t b1) {
    asm volatile(
        "mma.sync.aligned.m16n8k16.row.col.f32.bf16.bf16.f32 "
        "{%0,%1,%2,%3}, {%4,%5,%6,%7}, {%8,%9}, {%0,%1,%2,%3};"
        : "+f"(d0), "+f"(d1), "+f"(d2), "+f"(d3)
        : "r"(a0), "r"(a1), "r"(a2), "r"(a3), "r"(b0), "r"(b1));
}

__device__ __forceinline__ void ldm_x4(uint32_t& r0, uint32_t& r1,
                                       uint32_t& r2, uint32_t& r3, uint32_t saddr) {
    asm volatile("ldmatrix.sync.aligned.m8n8.x4.shared.b16 {%0,%1,%2,%3}, [%4];"
                 : "=r"(r0), "=r"(r1), "=r"(r2), "=r"(r3) : "r"(saddr));
}

// ---------------- smem layout (bytes) ----------------
// small weights: 1648 floats -> 6592 B, round to 6656
static constexpr int SM_W    = 0;
static constexpr int SM_AHI  = 6656;                    // BLK x 64 bf16, row stride 144B
static constexpr int SM_AMID = SM_AHI  + BLK * 144;     // 55296 each (BLK=384)
static constexpr int SM_BHI  = SM_AMID + BLK * 144;     // 256 n x 64 k bf16, stride 144B
static constexpr int SM_BMID = SM_BHI  + 256 * 144;
static constexpr int SM_TOTAL = SM_BMID + 256 * 144;    // = 190976 B
// PAR (D bounce, 12 warps x 32 rows x 34 f32 = 52224 B) aliases SM_AHI:
// A-hi region (55296 B) is dead after the A-fragment hoist; a __syncthreads()
// between hoist and first PAR write makes the aliasing race-free.
static constexpr int SM_PAR  = SM_AHI;

__global__ __launch_bounds__(BLK, 1)
void flow_kernel(const float* __restrict__ x,
                 const float* __restrict__ W0g, const float* __restrict__ b0g,
                 const float* __restrict__ W1g, const float* __restrict__ b1g,
                 const float* __restrict__ scaleg, const float* __restrict__ shiftg,
                 float* __restrict__ out, int B) {
    extern __shared__ __align__(16) char smem[];
    const uint32_t smb = (uint32_t)__cvta_generic_to_shared(smem);

    float* sW0 = (float*)(smem + SM_W);   // 256
    float* sb0 = sW0 + 256;               // 16
    float* sW1 = sb0 + 16;                // 1024
    float* sb1 = sW1 + 1024;              // 64
    float* ssc = sb1 + 64;                // 16
    float* ssh = ssc + 16;                // 16
    float* sbf = ssh + 16;                // 256

    const int tid  = threadIdx.x;
    const int w    = tid >> 5;            // warp id (0..11)
    const int lane = tid & 31;
    const int row  = blockIdx.x * BLK + tid;
    const bool valid = row < B;

    // per-lane ldmatrix address terms
    const uint32_t aterm = (uint32_t)(lane & 15) * 144u + (uint32_t)(lane >> 4) * 16u;
    const uint32_t bterm = (uint32_t)(lane & 7) * 144u + (uint32_t)(lane >> 3) * 16u;

    // z split by feature parity: za[t]=feat 2t, zb[t]=feat 2t+1
    float za[8], zb[8];
    if (valid) {
        const float4* xr = (const float4*)(x + (size_t)row * 16);
        #pragma unroll
        for (int qq = 0; qq < 4; qq++) {
            float4 v = xr[qq];
            za[2 * qq] = v.x;     zb[2 * qq] = v.y;
            za[2 * qq + 1] = v.z; zb[2 * qq + 1] = v.w;
        }
    } else {
        #pragma unroll
        for (int t = 0; t < 8; t++) { za[t] = 0.0f; zb[t] = 0.0f; }
    }

    float logdet = 0.0f;

    #pragma unroll 1
    for (int l = 7; l >= 0; --l) {
        __syncthreads();   // protect smem (incl. aliased PAR/A) from previous layer

        // -------- stage small weights + B tiles into smem --------
        if (tid < 256) sW0[tid] = W0g[l * 256 + tid];
        for (int i = tid; i < 1024; i += BLK) sW1[i] = W1g[l * 1024 + i];
        if (tid < 64) sb1[tid] = b1g[l * 64 + tid];
        if (tid < 16) {
            sb0[tid] = b0g[l * 16 + tid];
            ssc[tid] = scaleg[l * 16 + tid];
            ssh[tid] = shiftg[l * 16 + tid];
        }
        if (tid < 256) sbf[tid] = g_bf[l * 256 + tid];
        if (tid < 256) {
            // thread tid copies B row tid (64 bf16 = 8 uint4) for both parts
            const uint4* srcH = (const uint4*)(g_Bhi  + l * 16384) + tid * 8;
            const uint4* srcM = (const uint4*)(g_Bmid + l * 16384) + tid * 8;
            uint4* dstH = (uint4*)(smem + SM_BHI  + tid * 144);
            uint4* dstM = (uint4*)(smem + SM_BMID + tid * 144);
            #pragma unroll
            for (int i = 0; i < 8; i++) { dstH[i] = srcH[i]; dstM[i] = srcM[i]; }
        }
        __syncthreads();

        const int par = l & 1;

        // -------- stage 0: h0 = tanh(mz @ W0 + b0) --------
        float h0[16];
        #pragma unroll
        for (int j = 0; j < 16; ++j) {
            float a = sb0[j];
            #pragma unroll
            for (int t = 0; t < 8; ++t) {
                float zk = par ? za[t] : zb[t];     // kept parity = 1-par
                int fk = 2 * t + 1 - par;
                a += zk * sW0[fk * 16 + j];
            }
            h0[j] = fast_tanh(a);
        }

        // -------- stage 1: h1 = tanh(h0 @ W1 + b1) --------
        float h1[64];
        #pragma unroll
        for (int j = 0; j < 64; ++j) h1[j] = sb1[j];
        #pragma unroll
        for (int k = 0; k < 16; ++k) {
            float hk = h0[k];
            const float4* wr = (const float4*)(sW1 + k * 64);
            #pragma unroll
            for (int j4 = 0; j4 < 16; ++j4) {
                float4 wv = wr[j4];
                h1[4 * j4 + 0] += hk * wv.x;
                h1[4 * j4 + 1] += hk * wv.y;
                h1[4 * j4 + 2] += hk * wv.z;
                h1[4 * j4 + 3] += hk * wv.w;
            }
        }

        // -------- split h1 into bf16 hi/mid, store A rows to smem --------
        {
            uint32_t packH[32], packM[32];
            #pragma unroll
            for (int i = 0; i < 32; ++i) {
                float v0 = fast_tanh(h1[2 * i]);
                float v1 = fast_tanh(h1[2 * i + 1]);
                __nv_bfloat16 h0b = __float2bfloat16_rn(v0);
                __nv_bfloat16 h1b = __float2bfloat16_rn(v1);
                float r0 = v0 - __bfloat162float(h0b);
                float r1 = v1 - __bfloat162float(h1b);
                __nv_bfloat16 m0b = __float2bfloat16_rn(r0);
                __nv_bfloat16 m1b = __float2bfloat16_rn(r1);
                packH[i] = (uint32_t)__bfloat16_as_ushort(h0b) |
                           ((uint32_t)__bfloat16_as_ushort(h1b) << 16);
                packM[i] = (uint32_t)__bfloat16_as_ushort(m0b) |
                           ((uint32_t)__bfloat16_as_ushort(m1b) << 16);
            }
            uint4* dh = (uint4*)(smem + SM_AHI  + tid * 144);
            uint4* dm = (uint4*)(smem + SM_AMID + tid * 144);
            #pragma unroll
            for (int i = 0; i < 8; i++) {
                dh[i] = make_uint4(packH[4*i], packH[4*i+1], packH[4*i+2], packH[4*i+3]);
                dm[i] = make_uint4(packM[4*i], packM[4*i+1], packM[4*i+2], packM[4*i+3]);
            }
        }
        __syncthreads();

        // -------- hoist A fragments via ldmatrix (2 m-tiles, 4 k-steps, hi+mid) --
        uint32_t Ah[2][4][4], Am[2][4][4];
        #pragma unroll
        for (int m = 0; m < 2; ++m) {
            uint32_t rbase = (uint32_t)(32 * w + 16 * m) * 144u + aterm;
            #pragma unroll
            for (int ks = 0; ks < 4; ++ks) {
                ldm_x4(Ah[m][ks][0], Ah[m][ks][1], Ah[m][ks][2], Ah[m][ks][3],
                       smb + SM_AHI + rbase + (uint32_t)ks * 32u);
                ldm_x4(Am[m][ks][0], Am[m][ks][1], Am[m][ks][2], Am[m][ks][3],
                       smb + SM_AMID + rbase + (uint32_t)ks * 32u);
            }
        }
        __syncthreads();   // all warps done reading A-hi -> PAR aliasing now safe

        float* pwarp = (float*)(smem + SM_PAR + w * 4352);   // [32][34]

        // -------- per transformed feature: mma + spline --------
        #pragma unroll 1
        for (int t = 0; t < 8; ++t) {
            #pragma unroll
            for (int j = 0; j < 4; ++j) {
                // B fragments via ldmatrix: n-tile base = t*32 + 8j
                uint32_t nb = (uint32_t)(t * 32 + 8 * j) * 144u + bterm;
                uint32_t Bh[4][2], Bm[4][2];
                ldm_x4(Bh[0][0], Bh[0][1], Bh[1][0], Bh[1][1], smb + SM_BHI + nb);
                ldm_x4(Bh[2][0], Bh[2][1], Bh[3][0], Bh[3][1], smb + SM_BHI + nb + 64u);
                ldm_x4(Bm[0][0], Bm[0][1], Bm[1][0], Bm[1][1], smb + SM_BMID + nb);
                ldm_x4(Bm[2][0], Bm[2][1], Bm[3][0], Bm[3][1], smb + SM_BMID + nb + 64u);

                #pragma unroll
                for (int m = 0; m < 2; ++m) {
                    float d0 = 0.0f, d1 = 0.0f, d2 = 0.0f, d3 = 0.0f;
                    #pragma unroll
                    for (int ks = 0; ks < 4; ++ks) {
                        mma_bf16(d0, d1, d2, d3,
                                 Ah[m][ks][0], Ah[m][ks][1], Ah[m][ks][2], Ah[m][ks][3],
                                 Bh[ks][0], Bh[ks][1]);
                        mma_bf16(d0, d1, d2, d3,
                                 Ah[m][ks][0], Ah[m][ks][1], Ah[m][ks][2], Ah[m][ks][3],
                                 Bm[ks][0], Bm[ks][1]);
                        mma_bf16(d0, d1, d2, d3,
                                 Am[m][ks][0], Am[m][ks][1], Am[m][ks][2], Am[m][ks][3],
                                 Bh[ks][0], Bh[ks][1]);
                    }
                    // scatter D to padded params buffer (stride 34 -> 8B aligned)
                    int g = lane >> 2, q = lane & 3;
                    int r0 = 16 * m + g;
                    int c0 = 8 * j + 2 * q;
                    *(float2*)(pwarp + r0 * 34 + c0)       = make_float2(d0, d1);
                    *(float2*)(pwarp + (r0 + 8) * 34 + c0) = make_float2(d2, d3);
                }
            }
            __syncwarp();

            // gather this thread's row params + bias (float2)
            float acc[25];
            {
                const float2* pr = (const float2*)(pwarp + lane * 34);
                #pragma unroll
                for (int p = 0; p < 12; ++p) {
                    float2 v = pr[p];
                    acc[2 * p]     = v.x + sbf[t * 32 + 2 * p];
                    acc[2 * p + 1] = v.y + sbf[t * 32 + 2 * p + 1];
                }
                acc[24] = pwarp[lane * 34 + 24] + sbf[t * 32 + 24];
            }
            __syncwarp();   // params buffer free for next feature

            // ---- RQ spline forward + log-det ----
            float xv = par ? zb[t] : za[t];

            float mw = acc[0];
            #pragma unroll
            for (int k = 1; k < 8; ++k) mw = fmaxf(mw, acc[k]);
            float ew[8]; float swsum = 0.0f;
            #pragma unroll
            for (int k = 0; k < 8; ++k) { ew[k] = __expf(acc[k] - mw); swsum += ew[k]; }
            float cw = __fdividef(19.9992f, swsum);

            float mh = acc[8];
            #pragma unroll
            for (int k = 1; k < 8; ++k) mh = fmaxf(mh, acc[8 + k]);
            float eh[8]; float shsum = 0.0f;
            #pragma unroll
            for (int k = 0; k < 8; ++k) { eh[k] = __expf(acc[8 + k] - mh); shsum += eh[k]; }
            float chh = __fdividef(19.9992f, shsum);

            float cum = -10.0f, xk = -10.0f;
            int idx = 0;
            #pragma unroll
            for (int k = 0; k < 7; ++k) {
                cum += ew[k] * cw + 1e-4f;
                if (xv >= cum) { xk = cum; idx = k + 1; }
            }

            float yk = -10.0f, bh = 0.0f, bw = 1.0f, udk = 0.0f, udk1 = 0.0f;
            #pragma unroll
            for (int k = 0; k < 8; ++k) {
                float hh = eh[k] * chh + 1e-4f;
                if (k < idx) yk += hh;
                if (k == idx) {
                    bh = hh;
                    bw = ew[k] * cw + 1e-4f;
                    udk = acc[16 + k];
                    udk1 = acc[17 + k];
                }
            }

            float dk  = softplus_f(udk  + 0.54116665f) + 1e-4f;
            float dk1 = softplus_f(udk1 + 0.54116665f) + 1e-4f;
            float s   = __fdividef(bh, bw);
            float zt  = __saturatef(__fdividef(xv - xk, bw));
            float z1  = 1.0f - zt;
            float zz  = zt * zt;
            float zz1 = zt * z1;
            float den = s + (dk1 + dk - 2.0f * s) * zz1;
            float y   = yk + bh * __fdividef(s * zz + dk * zz1, den);
            float numld = dk1 * zz + 2.0f * s * zz1 + dk * z1 * z1;
            float ld = 2.0f * __logf(s) + __logf(numld) - 2.0f * __logf(den);

            bool outside = (xv <= -10.0f) || (xv >= 10.0f);
            if (outside) { y = xv; ld = 0.0f; }

            if (par) zb[t] = y; else za[t] = y;
            logdet += ld;
        }

        // -------- affine: z = z*scale + shift --------
        #pragma unroll
        for (int t = 0; t < 8; ++t) {
            za[t] = za[t] * ssc[2 * t]     + ssh[2 * t];
            zb[t] = zb[t] * ssc[2 * t + 1] + ssh[2 * t + 1];
        }
        logdet += g_lc[l];
    }

    float ss = 0.0f;
    #pragma unroll
    for (int t = 0; t < 8; ++t) ss += za[t] * za[t] + zb[t] * zb[t];

    if (valid) out[row] = -0.5f * ss - 14.703170f + logdet;   // 8*log(2*pi)
}

extern "C" void kernel_launch(void* const* d_in, const int* in_sizes, int n_in,
                              void* d_out, int out_size) {
    const float* x     = (const float*)d_in[0];
    const float* W0    = (const float*)d_in[1];
    const float* b0    = (const float*)d_in[2];
    const float* W1    = (const float*)d_in[3];
    const float* b1    = (const float*)d_in[4];
    const float* W2    = (const float*)d_in[5];
    const float* b2    = (const float*)d_in[6];
    const float* Wout  = (const float*)d_in[7];
    const float* bout  = (const float*)d_in[8];
    const float* scale = (const float*)d_in[9];
    const float* shift = (const float*)d_in[10];

    int B = in_sizes[0] / 16;

    const int NP = 8 * 256 * 64 + 8 * 256 + 8;
    precompute_kernel<<<(NP + 255) / 256, 256>>>(W2, b2, Wout, bout, scale);

    cudaFuncSetAttribute(flow_kernel, cudaFuncAttributeMaxDynamicSharedMemorySize, SM_TOTAL);
    flow_kernel<<<(B + BLK - 1) / BLK, BLK, SM_TOTAL>>>(
        x, W0, b0, W1, b1, scale, shift, (float*)d_out, B);
}